// round 3
// baseline (speedup 1.0000x reference)
#include <cuda_runtime.h>

// GINNet on GB300: CSR-based aggregation + fp32x2 SIMT GEMM with fused BN-stat
// epilogues. BN+ReLU folded into per-column affine applied at next consumer.

#define NN 100000
#define NE 1600000
#define DD 128
#define NG 64
#define AS_STRIDE 132
#define GEMM_SMEM ((DD*DD + 64*AS_STRIDE + 2*DD) * 4)

// ---------------- device scratch (allocation-free contract) ----------------
__device__ __align__(128) float g_z[NN * DD];   // aggregated features
__device__ __align__(128) float g_y[NN * DD];   // GEMM1 output (pre-BN1)
__device__ __align__(128) float g_h[NN * DD];   // GEMM2 output (pre-BN2)
__device__ int   g_cnt[NN];
__device__ int   g_ptr[NN + 1];
__device__ int   g_cur[NN];
__device__ int   g_srcs[NE];
__device__ float g_ssum[6][DD];
__device__ float g_ssq[6][DD];
__device__ __align__(16) float g_cA[6][DD];     // BN+ReLU affine scale
__device__ __align__(16) float g_cC[6][DD];     // BN+ReLU affine shift
__device__ float g_gsum[NG * DD];
__device__ int   g_gcnt[NG];
__device__ int   g_flags[2];                    // [0]=edge idx is64, [1]=batch is64

// ---------------- helpers ----------------
__device__ __forceinline__ int get_idx(const void* p, long long i, int is64) {
    if (is64) return (int)((const long long*)p)[i];
    return ((const int*)p)[i];
}

__device__ __forceinline__ unsigned long long pk2(float v) {
    unsigned long long r;
    asm("mov.b64 %0, {%1, %1};" : "=l"(r) : "f"(v));
    return r;
}
__device__ __forceinline__ void upk2(unsigned long long p, float& lo, float& hi) {
    asm("mov.b64 {%0, %1}, %2;" : "=f"(lo), "=f"(hi) : "l"(p));
}
__device__ __forceinline__ void fma2(unsigned long long& d, unsigned long long a,
                                     unsigned long long b) {
    asm("fma.rn.f32x2 %0, %1, %2, %0;" : "+l"(d) : "l"(a), "l"(b));
}

// ---------------- setup kernels ----------------
__global__ void k_zero() {
    int i = blockIdx.x * blockDim.x + threadIdx.x;
    if (i < NN) g_cnt[i] = 0;
    if (i < 6 * DD) { ((float*)g_ssum)[i] = 0.f; ((float*)g_ssq)[i] = 0.f; }
    if (i < NG * DD) g_gsum[i] = 0.f;
    if (i < NG) g_gcnt[i] = 0;
}

// Detect whether index buffers are int64 or int32 (JAX x64 ambiguity).
// Sample only within the first half (safe for both widths).
__global__ void k_detect(const void* ei, const void* bt) {
    __shared__ int bad[2];
    if (threadIdx.x < 2) bad[threadIdx.x] = 0;
    __syncthreads();
    const long long* pe = (const long long*)ei;
    const long long* pb = (const long long*)bt;
    for (int i = threadIdx.x; i < 4096; i += blockDim.x) {
        long long v = pe[(long long)i * 390];      // within first NE int64 slots
        if (v < 0 || v >= NN) atomicOr(&bad[0], 1);
        long long w = pb[(long long)i * 12];       // within first NN/2 int64 slots
        if (w < 0 || w >= NG) atomicOr(&bad[1], 1);
    }
    __syncthreads();
    if (threadIdx.x == 0) { g_flags[0] = bad[0] ? 0 : 1; g_flags[1] = bad[1] ? 0 : 1; }
}

__global__ void k_count(const void* ei) {
    int e = blockIdx.x * blockDim.x + threadIdx.x;
    if (e >= NE) return;
    int is64 = g_flags[0];
    int t = get_idx(ei, (long long)NE + e, is64);
    atomicAdd(&g_cnt[t], 1);
}

__global__ void k_scan() {  // single-block exclusive scan of g_cnt -> g_ptr/g_cur
    const int SEG = 98;     // 1024*98 >= NN
    int t = threadIdx.x;
    int beg = t * SEG;
    int end = min(beg + SEG, NN);
    int s = 0;
    for (int i = beg; i < end; i++) s += g_cnt[i];
    __shared__ int part[1024];
    part[t] = s;
    __syncthreads();
    for (int off = 1; off < 1024; off <<= 1) {
        int v = (t >= off) ? part[t - off] : 0;
        __syncthreads();
        part[t] += v;
        __syncthreads();
    }
    int run = (t == 0) ? 0 : part[t - 1];
    for (int i = beg; i < end; i++) {
        g_ptr[i] = run; g_cur[i] = run; run += g_cnt[i];
    }
    if (t == 1023) g_ptr[NN] = part[1023];
}

__global__ void k_fill(const void* ei) {
    int e = blockIdx.x * blockDim.x + threadIdx.x;
    if (e >= NE) return;
    int is64 = g_flags[0];
    int s = get_idx(ei, e, is64);
    int t = get_idx(ei, (long long)NE + e, is64);
    int pos = atomicAdd(&g_cur[t], 1);
    g_srcs[pos] = s;
}

// ---------------- aggregation: warp per node, no float atomics ----------------
// z[i] = (1+eps)*act(h[i]) + sum_{src in N(i)} act(h[src])
__global__ void k_agg(const float* __restrict__ x, int useX, int slot,
                      const float* __restrict__ epsArr, int layer) {
    int gt = blockIdx.x * blockDim.x + threadIdx.x;
    int node = gt >> 5;
    int lane = gt & 31;
    if (node >= NN) return;
    const float4* hin = useX ? (const float4*)x : (const float4*)g_h;
    float4 ca, cc;
    if (slot >= 0) {
        ca = ((const float4*)g_cA[slot])[lane];
        cc = ((const float4*)g_cC[slot])[lane];
    }
    float epsl = 1.f + epsArr[layer];
    int beg = g_ptr[node], end = g_ptr[node + 1];
    float4 v = hin[node * 32 + lane];
    if (slot >= 0) {
        v.x = fmaxf(fmaf(v.x, ca.x, cc.x), 0.f);
        v.y = fmaxf(fmaf(v.y, ca.y, cc.y), 0.f);
        v.z = fmaxf(fmaf(v.z, ca.z, cc.z), 0.f);
        v.w = fmaxf(fmaf(v.w, ca.w, cc.w), 0.f);
    }
    float4 acc = make_float4(v.x * epsl, v.y * epsl, v.z * epsl, v.w * epsl);
    for (int e = beg; e < end; e++) {
        int s = __ldg(&g_srcs[e]);
        float4 u = hin[s * 32 + lane];
        if (slot >= 0) {
            u.x = fmaxf(fmaf(u.x, ca.x, cc.x), 0.f);
            u.y = fmaxf(fmaf(u.y, ca.y, cc.y), 0.f);
            u.z = fmaxf(fmaf(u.z, ca.z, cc.z), 0.f);
            u.w = fmaxf(fmaf(u.w, ca.w, cc.w), 0.f);
        }
        acc.x += u.x; acc.y += u.y; acc.z += u.z; acc.w += u.w;
    }
    ((float4*)g_z)[node * 32 + lane] = acc;
}

// ---------------- GEMM: Y[64-row tile] = act(A) @ W, fused BN-stat epilogue ----
// 256 threads, each computes 4 rows x 8 cols via packed fma.rn.f32x2.
__global__ __launch_bounds__(256, 2)
void k_gemm(const float* __restrict__ W, int srcSel, int dstSel,
            int actSlot, int statSlot) {
    extern __shared__ float sm[];
    float* Bs = sm;                       // [128][128]
    float* As = sm + DD * DD;             // [64][AS_STRIDE]
    float* cs = As + 64 * AS_STRIDE;      // [128] col sums
    float* cq = cs + DD;                  // [128] col sumsq
    const float* A = srcSel ? g_y : g_z;
    float* Y = dstSel ? g_h : g_y;
    int tid = threadIdx.x;
    int tx = tid & 15, ty = tid >> 4;
    int mBase = blockIdx.x * 64;

    const float4* W4 = (const float4*)W;
    float4* Bs4 = (float4*)Bs;
#pragma unroll
    for (int i = 0; i < 16; i++) Bs4[tid + i * 256] = W4[tid + i * 256];

#pragma unroll
    for (int i = 0; i < 8; i++) {
        int lin = tid + i * 256;   // float4 index within tile
        int row = lin >> 5;
        int c4 = lin & 31;
        int grow = mBase + row;
        float4 v = make_float4(0.f, 0.f, 0.f, 0.f);
        if (grow < NN) v = ((const float4*)A)[grow * 32 + c4];
        if (actSlot >= 0) {
            float4 a = ((const float4*)g_cA[actSlot])[c4];
            float4 c = ((const float4*)g_cC[actSlot])[c4];
            v.x = fmaxf(fmaf(v.x, a.x, c.x), 0.f);
            v.y = fmaxf(fmaf(v.y, a.y, c.y), 0.f);
            v.z = fmaxf(fmaf(v.z, a.z, c.z), 0.f);
            v.w = fmaxf(fmaf(v.w, a.w, c.w), 0.f);
        }
        *(float4*)&As[row * AS_STRIDE + c4 * 4] = v;
    }
    if (tid < DD) { cs[tid] = 0.f; cq[tid] = 0.f; }
    __syncthreads();

    unsigned long long acc[4][4];
#pragma unroll
    for (int r = 0; r < 4; r++)
#pragma unroll
        for (int p = 0; p < 4; p++) acc[r][p] = 0ull;

    const float* Ar0 = &As[(ty * 4 + 0) * AS_STRIDE];
    const float* Ar1 = &As[(ty * 4 + 1) * AS_STRIDE];
    const float* Ar2 = &As[(ty * 4 + 2) * AS_STRIDE];
    const float* Ar3 = &As[(ty * 4 + 3) * AS_STRIDE];

#pragma unroll 8
    for (int k = 0; k < DD; k++) {
        unsigned long long a0 = pk2(Ar0[k]);
        unsigned long long a1 = pk2(Ar1[k]);
        unsigned long long a2 = pk2(Ar2[k]);
        unsigned long long a3 = pk2(Ar3[k]);
        const ulonglong2* brow = (const ulonglong2*)&Bs[k * DD];
        ulonglong2 b01 = brow[tx];        // cols 4tx..4tx+3
        ulonglong2 b23 = brow[16 + tx];   // cols 64+4tx..64+4tx+3
        fma2(acc[0][0], a0, b01.x); fma2(acc[0][1], a0, b01.y);
        fma2(acc[0][2], a0, b23.x); fma2(acc[0][3], a0, b23.y);
        fma2(acc[1][0], a1, b01.x); fma2(acc[1][1], a1, b01.y);
        fma2(acc[1][2], a1, b23.x); fma2(acc[1][3], a1, b23.y);
        fma2(acc[2][0], a2, b01.x); fma2(acc[2][1], a2, b01.y);
        fma2(acc[2][2], a2, b23.x); fma2(acc[2][3], a2, b23.y);
        fma2(acc[3][0], a3, b01.x); fma2(acc[3][1], a3, b01.y);
        fma2(acc[3][2], a3, b23.x); fma2(acc[3][3], a3, b23.y);
    }

    float ps[8], pq[8];
#pragma unroll
    for (int j = 0; j < 8; j++) { ps[j] = 0.f; pq[j] = 0.f; }

#pragma unroll
    for (int r = 0; r < 4; r++) {
        int grow = mBase + ty * 4 + r;
        if (grow < NN) {
            float f[8];
            upk2(acc[r][0], f[0], f[1]);
            upk2(acc[r][1], f[2], f[3]);
            upk2(acc[r][2], f[4], f[5]);
            upk2(acc[r][3], f[6], f[7]);
            ((float4*)Y)[grow * 32 + tx]      = make_float4(f[0], f[1], f[2], f[3]);
            ((float4*)Y)[grow * 32 + 16 + tx] = make_float4(f[4], f[5], f[6], f[7]);
#pragma unroll
            for (int j = 0; j < 8; j++) { ps[j] += f[j]; pq[j] += f[j] * f[j]; }
        }
    }
#pragma unroll
    for (int j = 0; j < 4; j++) {
        atomicAdd(&cs[tx * 4 + j], ps[j]);
        atomicAdd(&cq[tx * 4 + j], pq[j]);
        atomicAdd(&cs[64 + tx * 4 + j], ps[4 + j]);
        atomicAdd(&cq[64 + tx * 4 + j], pq[4 + j]);
    }
    __syncthreads();
    if (tid < DD) {
        atomicAdd(&g_ssum[statSlot][tid], cs[tid]);
        atomicAdd(&g_ssq[statSlot][tid], cq[tid]);
    }
}

// BN(train, biased var) folded into affine: y*a + c, ReLU applied by consumer.
__global__ void k_bnfin(const float* __restrict__ gamma,
                        const float* __restrict__ beta, int slot) {
    int d = threadIdx.x;
    float mean = g_ssum[slot][d] * (1.f / NN);
    float var = g_ssq[slot][d] * (1.f / NN) - mean * mean;
    float a = gamma[d] * rsqrtf(var + 1e-5f);
    g_cA[slot][d] = a;
    g_cC[slot][d] = beta[d] - mean * a;
}

// ---------------- readout ----------------
__global__ void k_nodeemb(float* __restrict__ out) {
    int i = blockIdx.x * blockDim.x + threadIdx.x;
    if (i >= NN * 32) return;
    int c4 = i & 31;
    float4 v = ((const float4*)g_h)[i];
    float4 a = ((const float4*)g_cA[5])[c4];
    float4 c = ((const float4*)g_cC[5])[c4];
    v.x = fmaxf(fmaf(v.x, a.x, c.x), 0.f);
    v.y = fmaxf(fmaf(v.y, a.y, c.y), 0.f);
    v.z = fmaxf(fmaf(v.z, a.z, c.z), 0.f);
    v.w = fmaxf(fmaf(v.w, a.w, c.w), 0.f);
    ((float4*)out)[i] = v;
}

__global__ void k_counts(const void* bt) {
    __shared__ int hist[NG];
    int tid = threadIdx.x;
    if (tid < NG) hist[tid] = 0;
    __syncthreads();
    int i = blockIdx.x * blockDim.x + tid;
    if (i < NN) {
        int b = get_idx(bt, i, g_flags[1]);
        atomicAdd(&hist[b], 1);
    }
    __syncthreads();
    if (tid < NG && hist[tid]) atomicAdd(&g_gcnt[tid], hist[tid]);
}

// Run-length accumulation over sorted batch -> few global atomics.
__global__ void k_gsum(const float* __restrict__ emb, const void* bt) {
    int d = threadIdx.x;            // 128 threads = columns
    int beg = blockIdx.x * 256;
    int end = min(beg + 256, NN);
    if (beg >= NN) return;
    int is64 = g_flags[1];
    int cur = get_idx(bt, beg, is64);
    float acc = 0.f;
    for (int i = beg; i < end; i++) {
        int b = get_idx(bt, i, is64);
        if (b != cur) { atomicAdd(&g_gsum[cur * DD + d], acc); acc = 0.f; cur = b; }
        acc += emb[i * DD + d];
    }
    atomicAdd(&g_gsum[cur * DD + d], acc);
}

__global__ void k_gemb(float* __restrict__ out) {
    int g = blockIdx.x, d = threadIdx.x;
    float cnt = (float)g_gcnt[g];
    float v = g_gsum[g * DD + d] / fmaxf(cnt, 1.f);
    float s = v * v;
#pragma unroll
    for (int o = 16; o > 0; o >>= 1) s += __shfl_xor_sync(0xffffffffu, s, o);
    __shared__ float red[4];
    if ((d & 31) == 0) red[d >> 5] = s;
    __syncthreads();
    float tot = red[0] + red[1] + red[2] + red[3];
    float nrm = fmaxf(sqrtf(tot), 1e-12f);
    out[NN * DD + g * DD + d] = v / nrm;
}

// ---------------- launch ----------------
extern "C" void kernel_launch(void* const* d_in, const int* in_sizes, int n_in,
                              void* d_out, int out_size) {
    const float* x  = (const float*)d_in[0];
    const void*  ei = d_in[1];
    const void*  bt = d_in[2];
    const float* W1 = (const float*)d_in[3];
    const float* g1 = (const float*)d_in[4];
    const float* b1 = (const float*)d_in[5];
    const float* W2 = (const float*)d_in[6];
    const float* g2 = (const float*)d_in[7];
    const float* b2 = (const float*)d_in[8];
    const float* eps = (const float*)d_in[9];
    float* out = (float*)d_out;
    (void)in_sizes; (void)n_in; (void)out_size;

    cudaFuncSetAttribute(k_gemm, cudaFuncAttributeMaxDynamicSharedMemorySize,
                         GEMM_SMEM);

    k_zero<<<(NN + 255) / 256, 256>>>();
    k_detect<<<1, 256>>>(ei, bt);
    k_count<<<(NE + 255) / 256, 256>>>(ei);
    k_scan<<<1, 1024>>>();
    k_fill<<<(NE + 255) / 256, 256>>>(ei);

    for (int l = 0; l < 3; l++) {
        k_agg<<<(NN * 32 + 255) / 256, 256>>>(x, l == 0 ? 1 : 0,
                                              l == 0 ? -1 : (2 * l - 1), eps, l);
        k_gemm<<<(NN + 63) / 64, 256, GEMM_SMEM>>>(W1 + l * DD * DD, 0, 0, -1, 2 * l);
        k_bnfin<<<1, DD>>>(g1 + l * DD, b1 + l * DD, 2 * l);
        k_gemm<<<(NN + 63) / 64, 256, GEMM_SMEM>>>(W2 + l * DD * DD, 1, 1, 2 * l,
                                                   2 * l + 1);
        k_bnfin<<<1, DD>>>(g2 + l * DD, b2 + l * DD, 2 * l + 1);
    }

    k_nodeemb<<<(NN * 32 + 255) / 256, 256>>>(out);
    k_counts<<<(NN + 255) / 256, 256>>>(bt);
    k_gsum<<<(NN + 255) / 256, 128>>>(out, bt);
    k_gemb<<<NG, DD>>>(out);
}